// round 2
// baseline (speedup 1.0000x reference)
#include <cuda_runtime.h>

// Problem constants: N=100000, E=3200000, FEAT=128, HID=32, EMB=16
#define NMAX 100000
#define EMAX 3200000
#define SCAN_B 1024
#define NBLK ((NMAX + SCAN_B - 1) / SCAN_B)   // 98

// ---- scratch (device globals; no allocation allowed) ----
__device__ float g_h1 [NMAX * 32];   // layer-1 transformed features
__device__ float g_hp1[NMAX * 32];   // layer-1 aggregated+relu output (h')
__device__ float g_als1[NMAX], g_ald1[NMAX];
__device__ float g_h2 [NMAX * 16];
__device__ float g_als2[NMAX], g_ald2[NMAX];

__device__ int g_deg [NMAX];
__device__ int g_scan[NMAX];
__device__ int g_off [NMAX];
__device__ int g_pos [NMAX];
__device__ int g_bsum [NBLK];
__device__ int g_bsumx[NBLK];
__device__ int g_esrc[EMAX];         // edge srcs grouped by dst

__device__ __forceinline__ float leaky(float a) { return a > 0.0f ? a : 0.2f * a; }

// ===========================================================================
// CSR build: histogram -> scan -> permute
// ===========================================================================
__global__ __launch_bounds__(256) void hist_zero(int N) {
    int i = blockIdx.x * 256 + threadIdx.x;
    if (i < N) g_deg[i] = 0;
}

__global__ __launch_bounds__(256) void hist_kernel(const int* __restrict__ dst, int E) {
    int e = blockIdx.x * 256 + threadIdx.x;
    if (e < E) atomicAdd(&g_deg[__ldg(dst + e)], 1);
}

__global__ __launch_bounds__(SCAN_B) void scan1_kernel(int N) {
    __shared__ int sh[SCAN_B];
    int gid = blockIdx.x * SCAN_B + threadIdx.x;
    int v = (gid < N) ? g_deg[gid] : 0;
    sh[threadIdx.x] = v;
    __syncthreads();
#pragma unroll
    for (int o = 1; o < SCAN_B; o <<= 1) {
        int t = (threadIdx.x >= o) ? sh[threadIdx.x - o] : 0;
        __syncthreads();
        sh[threadIdx.x] += t;
        __syncthreads();
    }
    if (gid < N) g_scan[gid] = sh[threadIdx.x];
    if (threadIdx.x == SCAN_B - 1) g_bsum[blockIdx.x] = sh[SCAN_B - 1];
}

__global__ void scan2_kernel(int nb) {
    if (threadIdx.x == 0 && blockIdx.x == 0) {
        int run = 0;
        for (int i = 0; i < nb; i++) { g_bsumx[i] = run; run += g_bsum[i]; }
    }
}

__global__ __launch_bounds__(256) void scan3_kernel(int N) {
    int gid = blockIdx.x * 256 + threadIdx.x;
    if (gid < N) {
        int off = g_scan[gid] - g_deg[gid] + g_bsumx[gid / SCAN_B];
        g_off[gid] = off;
        g_pos[gid] = off;
    }
}

__global__ __launch_bounds__(256) void permute_kernel(
    const int* __restrict__ src, const int* __restrict__ dst, int E)
{
    int e = blockIdx.x * 256 + threadIdx.x;
    if (e >= E) return;
    int d = __ldg(dst + e);
    int p = atomicAdd(&g_pos[d], 1);
    g_esrc[p] = __ldg(src + e);
}

// ===========================================================================
// K1: h1 = x @ W1; al_s1/al_d1
// ===========================================================================
__global__ __launch_bounds__(256) void node1_kernel(
    const float* __restrict__ x, const float* __restrict__ W1,
    const float* __restrict__ asrc, const float* __restrict__ adst, int N)
{
    __shared__ float Ws[128 * 32];
    __shared__ float s_as[32], s_ad[32];
    for (int i = threadIdx.x; i < 128 * 32; i += 256) Ws[i] = W1[i];
    if (threadIdx.x < 32) { s_as[threadIdx.x] = asrc[threadIdx.x]; s_ad[threadIdx.x] = adst[threadIdx.x]; }
    __syncthreads();

    int n = blockIdx.x * 256 + threadIdx.x;
    if (n >= N) return;

    float4 acc[8];
#pragma unroll
    for (int i = 0; i < 8; i++) acc[i] = make_float4(0.f, 0.f, 0.f, 0.f);

    const float4* xr = reinterpret_cast<const float4*>(x + (size_t)n * 128);
#pragma unroll 4
    for (int k4 = 0; k4 < 32; k4++) {
        float4 xv = __ldg(&xr[k4]);
        float xk[4] = {xv.x, xv.y, xv.z, xv.w};
#pragma unroll
        for (int kk = 0; kk < 4; kk++) {
            const float4* wr = reinterpret_cast<const float4*>(&Ws[(k4 * 4 + kk) * 32]);
            float xs = xk[kk];
#pragma unroll
            for (int c4 = 0; c4 < 8; c4++) {
                float4 w = wr[c4];
                acc[c4].x += xs * w.x; acc[c4].y += xs * w.y;
                acc[c4].z += xs * w.z; acc[c4].w += xs * w.w;
            }
        }
    }

    float als = 0.f, ald = 0.f;
#pragma unroll
    for (int c4 = 0; c4 < 8; c4++) {
        float4 a  = acc[c4];
        float4 s4 = reinterpret_cast<const float4*>(s_as)[c4];
        float4 d4 = reinterpret_cast<const float4*>(s_ad)[c4];
        als += a.x * s4.x + a.y * s4.y + a.z * s4.z + a.w * s4.w;
        ald += a.x * d4.x + a.y * d4.y + a.z * d4.z + a.w * d4.w;
    }
    g_als1[n] = als; g_ald1[n] = ald;

    float4* hp = reinterpret_cast<float4*>(&g_h1[n * 32]);
#pragma unroll
    for (int c4 = 0; c4 < 8; c4++) hp[c4] = acc[c4];
}

// ===========================================================================
// K2: layer-1 aggregate. Warp per destination node; lane = channel (32).
// h'(n) = relu( (sum_e w_e h1[src_e] + w_self h1[n]) / (sum w + eps) + b1 )
// ===========================================================================
__global__ __launch_bounds__(256) void agg1_kernel(const float* __restrict__ b1, int N)
{
    int wid = (blockIdx.x * 256 + threadIdx.x) >> 5;
    int lane = threadIdx.x & 31;
    if (wid >= N) return;
    int n = wid;

    float ald = __ldg(&g_ald1[n]);
    int start = g_off[n];
    int end = start + g_deg[n];

    float acc = 0.f, den = 0.f;
    for (int base = start; base < end; base += 32) {
        int idx = base + lane;
        int s = 0; float w = 0.f;
        if (idx < end) {
            s = __ldg(&g_esrc[idx]);
            w = __expf(leaky(__ldg(&g_als1[s]) + ald));
        }
        den += w;
        int mm = end - base; if (mm > 32) mm = 32;
        if (mm == 32) {
#pragma unroll 4
            for (int j = 0; j < 32; j++) {
                int   sj = __shfl_sync(0xffffffffu, s, j);
                float wj = __shfl_sync(0xffffffffu, w, j);
                acc = fmaf(wj, __ldg(&g_h1[sj * 32 + lane]), acc);
            }
        } else {
            for (int j = 0; j < mm; j++) {
                int   sj = __shfl_sync(0xffffffffu, s, j);
                float wj = __shfl_sync(0xffffffffu, w, j);
                acc = fmaf(wj, __ldg(&g_h1[sj * 32 + lane]), acc);
            }
        }
    }
#pragma unroll
    for (int o = 16; o; o >>= 1) den += __shfl_xor_sync(0xffffffffu, den, o);

    float wself = __expf(leaky(__ldg(&g_als1[n]) + ald));
    den += wself;
    acc = fmaf(wself, __ldg(&g_h1[n * 32 + lane]), acc);

    float inv = 1.0f / (den + 1e-16f);
    g_hp1[n * 32 + lane] = fmaxf(fmaf(acc, inv, __ldg(&b1[lane])), 0.f);
}

// ===========================================================================
// K3: h2 = h' @ W2; al_s2/al_d2
// ===========================================================================
__global__ __launch_bounds__(256) void node2_kernel(
    const float* __restrict__ W2,
    const float* __restrict__ asrc, const float* __restrict__ adst, int N)
{
    __shared__ float Ws[32 * 16];
    __shared__ float s_as[16], s_ad[16];
    for (int i = threadIdx.x; i < 32 * 16; i += 256) Ws[i] = W2[i];
    if (threadIdx.x < 16) { s_as[threadIdx.x] = asrc[threadIdx.x]; s_ad[threadIdx.x] = adst[threadIdx.x]; }
    __syncthreads();

    int n = blockIdx.x * 256 + threadIdx.x;
    if (n >= N) return;

    float4 h2[4];
#pragma unroll
    for (int i = 0; i < 4; i++) h2[i] = make_float4(0.f, 0.f, 0.f, 0.f);

    const float4* hp = reinterpret_cast<const float4*>(&g_hp1[n * 32]);
#pragma unroll
    for (int c4 = 0; c4 < 8; c4++) {
        float4 xv = hp[c4];
        float xk[4] = {xv.x, xv.y, xv.z, xv.w};
#pragma unroll
        for (int kk = 0; kk < 4; kk++) {
            const float4* wr = reinterpret_cast<const float4*>(&Ws[(c4 * 4 + kk) * 16]);
            float xs = xk[kk];
#pragma unroll
            for (int o4 = 0; o4 < 4; o4++) {
                float4 w = wr[o4];
                h2[o4].x += xs * w.x; h2[o4].y += xs * w.y;
                h2[o4].z += xs * w.z; h2[o4].w += xs * w.w;
            }
        }
    }

    float als = 0.f, ald = 0.f;
#pragma unroll
    for (int o4 = 0; o4 < 4; o4++) {
        float4 a  = h2[o4];
        float4 s4 = reinterpret_cast<const float4*>(s_as)[o4];
        float4 d4 = reinterpret_cast<const float4*>(s_ad)[o4];
        als += a.x * s4.x + a.y * s4.y + a.z * s4.z + a.w * s4.w;
        ald += a.x * d4.x + a.y * d4.y + a.z * d4.z + a.w * d4.w;
    }
    g_als2[n] = als; g_ald2[n] = ald;

    float4* out = reinterpret_cast<float4*>(&g_h2[n * 16]);
#pragma unroll
    for (int o4 = 0; o4 < 4; o4++) out[o4] = h2[o4];
}

// ===========================================================================
// K4: layer-2 aggregate + final output. Warp per node.
// Lanes use channel c = lane&15; both half-warps compute identical sums
// (redundant, harmless). Batch of 32 edge weights computed across full warp.
// ===========================================================================
__global__ __launch_bounds__(256) void agg2_kernel(
    const float* __restrict__ b2, float* __restrict__ out, int N)
{
    int wid = (blockIdx.x * 256 + threadIdx.x) >> 5;
    int lane = threadIdx.x & 31;
    if (wid >= N) return;
    int n = wid;
    int c = lane & 15;

    float ald = __ldg(&g_ald2[n]);
    int start = g_off[n];
    int end = start + g_deg[n];

    float acc = 0.f, den = 0.f;
    for (int base = start; base < end; base += 32) {
        int idx = base + lane;
        int s = 0; float w = 0.f;
        if (idx < end) {
            s = __ldg(&g_esrc[idx]);
            w = __expf(leaky(__ldg(&g_als2[s]) + ald));
        }
        den += w;
        int mm = end - base; if (mm > 32) mm = 32;
        if (mm == 32) {
#pragma unroll 4
            for (int j = 0; j < 32; j++) {
                int   sj = __shfl_sync(0xffffffffu, s, j);
                float wj = __shfl_sync(0xffffffffu, w, j);
                acc = fmaf(wj, __ldg(&g_h2[sj * 16 + c]), acc);
            }
        } else {
            for (int j = 0; j < mm; j++) {
                int   sj = __shfl_sync(0xffffffffu, s, j);
                float wj = __shfl_sync(0xffffffffu, w, j);
                acc = fmaf(wj, __ldg(&g_h2[sj * 16 + c]), acc);
            }
        }
    }
#pragma unroll
    for (int o = 16; o; o >>= 1) den += __shfl_xor_sync(0xffffffffu, den, o);

    float wself = __expf(leaky(__ldg(&g_als2[n]) + ald));
    den += wself;
    acc = fmaf(wself, __ldg(&g_h2[n * 16 + c]), acc);

    float inv = 1.0f / (den + 1e-16f);
    if (lane < 16)
        out[n * 16 + c] = fmaf(acc, inv, __ldg(&b2[c]));
}

// ===========================================================================
extern "C" void kernel_launch(void* const* d_in, const int* in_sizes, int n_in,
                              void* d_out, int out_size)
{
    const float* x   = (const float*)d_in[0];
    const int*   ei  = (const int*)  d_in[1];
    // d_in[2] = ew, unused (edge_dim=None)
    const float* W1  = (const float*)d_in[3];
    const float* as1 = (const float*)d_in[4];
    const float* ad1 = (const float*)d_in[5];
    const float* b1  = (const float*)d_in[6];
    const float* W2  = (const float*)d_in[7];
    const float* as2 = (const float*)d_in[8];
    const float* ad2 = (const float*)d_in[9];
    const float* b2  = (const float*)d_in[10];

    int N = in_sizes[0] / 128;
    int E = in_sizes[1] / 2;
    const int* src = ei;
    const int* dst = ei + E;

    int nblkN  = (N + 255) / 256;
    int nblkE  = (E + 255) / 256;
    int nscan  = (N + SCAN_B - 1) / SCAN_B;
    int nwarpN = (N * 32 + 255) / 256;

    // CSR build (shared by both layers)
    hist_zero   <<<nblkN, 256>>>(N);
    hist_kernel <<<nblkE, 256>>>(dst, E);
    scan1_kernel<<<nscan, SCAN_B>>>(N);
    scan2_kernel<<<1, 32>>>(nscan);
    scan3_kernel<<<nblkN, 256>>>(N);
    permute_kernel<<<nblkE, 256>>>(src, dst, E);

    // Layer 1
    node1_kernel<<<nblkN, 256>>>(x, W1, as1, ad1, N);
    agg1_kernel <<<nwarpN, 256>>>(b1, N);

    // Layer 2
    node2_kernel<<<nblkN, 256>>>(W2, as2, ad2, N);
    agg2_kernel <<<nwarpN, 256>>>(b2, (float*)d_out, N);
}

// round 3
// speedup vs baseline: 1.1359x; 1.1359x over previous
#include <cuda_runtime.h>

// Problem constants: N=100000, E=3200000, FEAT=128, HID=32, EMB=16
#define NMAX 100000
#define EMAX 3200000
#define SCAN_B 1024
#define NBLK ((NMAX + SCAN_B - 1) / SCAN_B)   // 98

// ---- scratch (device globals; no allocation allowed) ----
__device__ float g_h1 [NMAX * 32];
__device__ float g_hp1[NMAX * 32];
__device__ float g_als1[NMAX], g_ald1[NMAX];
__device__ float g_h2 [NMAX * 16];
__device__ float g_als2[NMAX], g_ald2[NMAX];

__device__ int g_deg [NMAX];
__device__ int g_scan[NMAX];
__device__ int g_off [NMAX];
__device__ int g_pos [NMAX];
__device__ int g_bsum [NBLK];
__device__ int g_bsumx[NBLK];
__device__ int g_esrc[EMAX];

__device__ __forceinline__ float leaky(float a) { return a > 0.0f ? a : 0.2f * a; }

// ===========================================================================
// CSR build
// ===========================================================================
__global__ __launch_bounds__(256) void hist_zero(int N) {
    int i = blockIdx.x * 256 + threadIdx.x;
    if (i < N) g_deg[i] = 0;
}

__global__ __launch_bounds__(256) void hist_kernel(const int* __restrict__ dst, int E) {
    int e = blockIdx.x * 256 + threadIdx.x;
    if (e < E) atomicAdd(&g_deg[__ldg(dst + e)], 1);
}

__global__ __launch_bounds__(SCAN_B) void scan1_kernel(int N) {
    __shared__ int sh[SCAN_B];
    int gid = blockIdx.x * SCAN_B + threadIdx.x;
    int v = (gid < N) ? g_deg[gid] : 0;
    sh[threadIdx.x] = v;
    __syncthreads();
#pragma unroll
    for (int o = 1; o < SCAN_B; o <<= 1) {
        int t = (threadIdx.x >= o) ? sh[threadIdx.x - o] : 0;
        __syncthreads();
        sh[threadIdx.x] += t;
        __syncthreads();
    }
    if (gid < N) g_scan[gid] = sh[threadIdx.x];
    if (threadIdx.x == SCAN_B - 1) g_bsum[blockIdx.x] = sh[SCAN_B - 1];
}

// parallel exclusive scan of <=128 block sums, single block
__global__ __launch_bounds__(128) void scan2_kernel(int nb) {
    __shared__ int sh[128];
    int t = threadIdx.x;
    int v = (t < nb) ? g_bsum[t] : 0;
    sh[t] = v;
    __syncthreads();
#pragma unroll
    for (int o = 1; o < 128; o <<= 1) {
        int u = (t >= o) ? sh[t - o] : 0;
        __syncthreads();
        sh[t] += u;
        __syncthreads();
    }
    if (t < nb) g_bsumx[t] = sh[t] - v;   // exclusive prefix
}

__global__ __launch_bounds__(256) void scan3_kernel(int N) {
    int gid = blockIdx.x * 256 + threadIdx.x;
    if (gid < N) {
        int off = g_scan[gid] - g_deg[gid] + g_bsumx[gid / SCAN_B];
        g_off[gid] = off;
        g_pos[gid] = off;
    }
}

__global__ __launch_bounds__(256) void permute_kernel(
    const int* __restrict__ src, const int* __restrict__ dst, int E)
{
    int e = blockIdx.x * 256 + threadIdx.x;
    if (e >= E) return;
    int d = __ldg(dst + e);
    int p = atomicAdd(&g_pos[d], 1);
    g_esrc[p] = __ldg(src + e);
}

// ===========================================================================
// K1: h1 = x @ W1; al_s1/al_d1. Two nodes per thread (halves LDS traffic).
// ===========================================================================
__global__ __launch_bounds__(256) void node1_kernel(
    const float* __restrict__ x, const float* __restrict__ W1,
    const float* __restrict__ asrc, const float* __restrict__ adst, int N)
{
    __shared__ float Ws[128 * 32];
    __shared__ float s_as[32], s_ad[32];
    for (int i = threadIdx.x; i < 128 * 32; i += 256) Ws[i] = W1[i];
    if (threadIdx.x < 32) { s_as[threadIdx.x] = asrc[threadIdx.x]; s_ad[threadIdx.x] = adst[threadIdx.x]; }
    __syncthreads();

    int n0 = blockIdx.x * 512 + threadIdx.x;
    int n1 = n0 + 256;
    if (n0 >= N) return;
    bool v1 = (n1 < N);
    int n1c = v1 ? n1 : n0;

    float4 acc0[8], acc1[8];
#pragma unroll
    for (int i = 0; i < 8; i++) { acc0[i] = make_float4(0.f,0.f,0.f,0.f); acc1[i] = make_float4(0.f,0.f,0.f,0.f); }

    const float4* xr0 = reinterpret_cast<const float4*>(x + (size_t)n0  * 128);
    const float4* xr1 = reinterpret_cast<const float4*>(x + (size_t)n1c * 128);
#pragma unroll 2
    for (int k4 = 0; k4 < 32; k4++) {
        float4 xv0 = __ldg(&xr0[k4]);
        float4 xv1 = __ldg(&xr1[k4]);
        float xk0[4] = {xv0.x, xv0.y, xv0.z, xv0.w};
        float xk1[4] = {xv1.x, xv1.y, xv1.z, xv1.w};
#pragma unroll
        for (int kk = 0; kk < 4; kk++) {
            const float4* wr = reinterpret_cast<const float4*>(&Ws[(k4 * 4 + kk) * 32]);
            float xs0 = xk0[kk], xs1 = xk1[kk];
#pragma unroll
            for (int c4 = 0; c4 < 8; c4++) {
                float4 w = wr[c4];
                acc0[c4].x = fmaf(xs0, w.x, acc0[c4].x); acc0[c4].y = fmaf(xs0, w.y, acc0[c4].y);
                acc0[c4].z = fmaf(xs0, w.z, acc0[c4].z); acc0[c4].w = fmaf(xs0, w.w, acc0[c4].w);
                acc1[c4].x = fmaf(xs1, w.x, acc1[c4].x); acc1[c4].y = fmaf(xs1, w.y, acc1[c4].y);
                acc1[c4].z = fmaf(xs1, w.z, acc1[c4].z); acc1[c4].w = fmaf(xs1, w.w, acc1[c4].w);
            }
        }
    }

    float als0 = 0.f, ald0 = 0.f, als1v = 0.f, ald1v = 0.f;
#pragma unroll
    for (int c4 = 0; c4 < 8; c4++) {
        float4 s4 = reinterpret_cast<const float4*>(s_as)[c4];
        float4 d4 = reinterpret_cast<const float4*>(s_ad)[c4];
        float4 a = acc0[c4];
        als0 += a.x*s4.x + a.y*s4.y + a.z*s4.z + a.w*s4.w;
        ald0 += a.x*d4.x + a.y*d4.y + a.z*d4.z + a.w*d4.w;
        float4 b = acc1[c4];
        als1v += b.x*s4.x + b.y*s4.y + b.z*s4.z + b.w*s4.w;
        ald1v += b.x*d4.x + b.y*d4.y + b.z*d4.z + b.w*d4.w;
    }
    g_als1[n0] = als0; g_ald1[n0] = ald0;
    float4* hp0 = reinterpret_cast<float4*>(&g_h1[n0 * 32]);
#pragma unroll
    for (int c4 = 0; c4 < 8; c4++) hp0[c4] = acc0[c4];
    if (v1) {
        g_als1[n1] = als1v; g_ald1[n1] = ald1v;
        float4* hp1 = reinterpret_cast<float4*>(&g_h1[n1 * 32]);
#pragma unroll
        for (int c4 = 0; c4 < 8; c4++) hp1[c4] = acc1[c4];
    }
}

// ===========================================================================
// K2: layer-1 aggregate. Warp per node, lane = channel, 4-way MLP inner loop.
// ===========================================================================
__global__ __launch_bounds__(256) void agg1_kernel(const float* __restrict__ b1, int N)
{
    int wid = (blockIdx.x * 256 + threadIdx.x) >> 5;
    int lane = threadIdx.x & 31;
    if (wid >= N) return;
    int n = wid;

    float ald = __ldg(&g_ald1[n]);
    int start = g_off[n];
    int end = start + g_deg[n];

    float a0 = 0.f, a1 = 0.f, a2 = 0.f, a3 = 0.f, den = 0.f;
    for (int base = start; base < end; base += 32) {
        int idx = base + lane;
        int s = 0; float w = 0.f;
        if (idx < end) {
            s = __ldg(&g_esrc[idx]);
            w = __expf(leaky(__ldg(&g_als1[s]) + ald));
        }
        den += w;
        int mm = end - base; if (mm > 32) mm = 32;
        if (mm == 32) {
#pragma unroll
            for (int j = 0; j < 32; j += 4) {
                int   s0 = __shfl_sync(0xffffffffu, s, j);
                int   s1 = __shfl_sync(0xffffffffu, s, j + 1);
                int   s2 = __shfl_sync(0xffffffffu, s, j + 2);
                int   s3 = __shfl_sync(0xffffffffu, s, j + 3);
                float w0 = __shfl_sync(0xffffffffu, w, j);
                float w1 = __shfl_sync(0xffffffffu, w, j + 1);
                float w2 = __shfl_sync(0xffffffffu, w, j + 2);
                float w3 = __shfl_sync(0xffffffffu, w, j + 3);
                float f0 = __ldg(&g_h1[s0 * 32 + lane]);
                float f1 = __ldg(&g_h1[s1 * 32 + lane]);
                float f2 = __ldg(&g_h1[s2 * 32 + lane]);
                float f3 = __ldg(&g_h1[s3 * 32 + lane]);
                a0 = fmaf(w0, f0, a0); a1 = fmaf(w1, f1, a1);
                a2 = fmaf(w2, f2, a2); a3 = fmaf(w3, f3, a3);
            }
        } else {
            for (int j = 0; j < mm; j++) {
                int   sj = __shfl_sync(0xffffffffu, s, j);
                float wj = __shfl_sync(0xffffffffu, w, j);
                a0 = fmaf(wj, __ldg(&g_h1[sj * 32 + lane]), a0);
            }
        }
    }
    float acc = (a0 + a1) + (a2 + a3);
#pragma unroll
    for (int o = 16; o; o >>= 1) den += __shfl_xor_sync(0xffffffffu, den, o);

    float wself = __expf(leaky(__ldg(&g_als1[n]) + ald));
    den += wself;
    acc = fmaf(wself, __ldg(&g_h1[n * 32 + lane]), acc);

    float inv = 1.0f / (den + 1e-16f);
    g_hp1[n * 32 + lane] = fmaxf(fmaf(acc, inv, __ldg(&b1[lane])), 0.f);
}

// ===========================================================================
// K3: h2 = h' @ W2; al_s2/al_d2
// ===========================================================================
__global__ __launch_bounds__(256) void node2_kernel(
    const float* __restrict__ W2,
    const float* __restrict__ asrc, const float* __restrict__ adst, int N)
{
    __shared__ float Ws[32 * 16];
    __shared__ float s_as[16], s_ad[16];
    for (int i = threadIdx.x; i < 32 * 16; i += 256) Ws[i] = W2[i];
    if (threadIdx.x < 16) { s_as[threadIdx.x] = asrc[threadIdx.x]; s_ad[threadIdx.x] = adst[threadIdx.x]; }
    __syncthreads();

    int n = blockIdx.x * 256 + threadIdx.x;
    if (n >= N) return;

    float4 h2[4];
#pragma unroll
    for (int i = 0; i < 4; i++) h2[i] = make_float4(0.f, 0.f, 0.f, 0.f);

    const float4* hp = reinterpret_cast<const float4*>(&g_hp1[n * 32]);
#pragma unroll
    for (int c4 = 0; c4 < 8; c4++) {
        float4 xv = hp[c4];
        float xk[4] = {xv.x, xv.y, xv.z, xv.w};
#pragma unroll
        for (int kk = 0; kk < 4; kk++) {
            const float4* wr = reinterpret_cast<const float4*>(&Ws[(c4 * 4 + kk) * 16]);
            float xs = xk[kk];
#pragma unroll
            for (int o4 = 0; o4 < 4; o4++) {
                float4 w = wr[o4];
                h2[o4].x = fmaf(xs, w.x, h2[o4].x); h2[o4].y = fmaf(xs, w.y, h2[o4].y);
                h2[o4].z = fmaf(xs, w.z, h2[o4].z); h2[o4].w = fmaf(xs, w.w, h2[o4].w);
            }
        }
    }

    float als = 0.f, ald = 0.f;
#pragma unroll
    for (int o4 = 0; o4 < 4; o4++) {
        float4 a  = h2[o4];
        float4 s4 = reinterpret_cast<const float4*>(s_as)[o4];
        float4 d4 = reinterpret_cast<const float4*>(s_ad)[o4];
        als += a.x*s4.x + a.y*s4.y + a.z*s4.z + a.w*s4.w;
        ald += a.x*d4.x + a.y*d4.y + a.z*d4.z + a.w*d4.w;
    }
    g_als2[n] = als; g_ald2[n] = ald;

    float4* out = reinterpret_cast<float4*>(&g_h2[n * 16]);
#pragma unroll
    for (int o4 = 0; o4 < 4; o4++) out[o4] = h2[o4];
}

// ===========================================================================
// K4: layer-2 aggregate + output. TWO nodes per warp (16 lanes each).
// ===========================================================================
__global__ __launch_bounds__(256) void agg2_kernel(
    const float* __restrict__ b2, float* __restrict__ out, int N)
{
    int wid = (blockIdx.x * 256 + threadIdx.x) >> 5;
    int lane = threadIdx.x & 31;
    int half = lane >> 4;
    int c = lane & 15;
    int n = wid * 2 + half;
    if (wid * 2 >= N) return;
    bool nvalid = (n < N);
    int nn = nvalid ? n : (N - 1);

    float ald = __ldg(&g_ald2[nn]);
    int start = g_off[nn];
    int deg = g_deg[nn];
    int end = start + deg;

    int nb = (deg + 15) >> 4;
    int nbo = __shfl_xor_sync(0xffffffffu, nb, 16);
    int nbmax = nb > nbo ? nb : nbo;

    float a0 = 0.f, a1 = 0.f, den = 0.f;
    for (int b = 0; b < nbmax; b++) {
        int idx = start + b * 16 + c;
        int s = 0; float w = 0.f;
        if (nvalid && idx < end) {
            s = __ldg(&g_esrc[idx]);
            w = __expf(leaky(__ldg(&g_als2[s]) + ald));
        }
        den += w;
#pragma unroll
        for (int j = 0; j < 16; j += 2) {
            int   s0 = __shfl_sync(0xffffffffu, s, j, 16);
            int   s1 = __shfl_sync(0xffffffffu, s, j + 1, 16);
            float w0 = __shfl_sync(0xffffffffu, w, j, 16);
            float w1 = __shfl_sync(0xffffffffu, w, j + 1, 16);
            float f0 = (w0 != 0.f) ? __ldg(&g_h2[s0 * 16 + c]) : 0.f;
            float f1 = (w1 != 0.f) ? __ldg(&g_h2[s1 * 16 + c]) : 0.f;
            a0 = fmaf(w0, f0, a0);
            a1 = fmaf(w1, f1, a1);
        }
    }
    float acc = a0 + a1;
#pragma unroll
    for (int o = 8; o; o >>= 1) den += __shfl_xor_sync(0xffffffffu, den, o, 16);

    float wself = __expf(leaky(__ldg(&g_als2[nn]) + ald));
    den += wself;
    acc = fmaf(wself, __ldg(&g_h2[nn * 16 + c]), acc);

    float inv = 1.0f / (den + 1e-16f);
    if (nvalid)
        out[n * 16 + c] = fmaf(acc, inv, __ldg(&b2[c]));
}

// ===========================================================================
extern "C" void kernel_launch(void* const* d_in, const int* in_sizes, int n_in,
                              void* d_out, int out_size)
{
    const float* x   = (const float*)d_in[0];
    const int*   ei  = (const int*)  d_in[1];
    const float* W1  = (const float*)d_in[3];
    const float* as1 = (const float*)d_in[4];
    const float* ad1 = (const float*)d_in[5];
    const float* b1  = (const float*)d_in[6];
    const float* W2  = (const float*)d_in[7];
    const float* as2 = (const float*)d_in[8];
    const float* ad2 = (const float*)d_in[9];
    const float* b2  = (const float*)d_in[10];

    int N = in_sizes[0] / 128;
    int E = in_sizes[1] / 2;
    const int* src = ei;
    const int* dst = ei + E;

    int nblkN  = (N + 255) / 256;
    int nblkE  = (E + 255) / 256;
    int nscan  = (N + SCAN_B - 1) / SCAN_B;
    int nwarp1 = (N * 32 + 255) / 256;
    int nwarp2 = (((N + 1) / 2) * 32 + 255) / 256;

    // CSR build (shared by both layers)
    hist_zero   <<<nblkN, 256>>>(N);
    hist_kernel <<<nblkE, 256>>>(dst, E);
    scan1_kernel<<<nscan, SCAN_B>>>(N);
    scan2_kernel<<<1, 128>>>(nscan);
    scan3_kernel<<<nblkN, 256>>>(N);
    permute_kernel<<<nblkE, 256>>>(src, dst, E);

    // Layer 1
    node1_kernel<<<(N + 511) / 512, 256>>>(x, W1, as1, ad1, N);
    agg1_kernel <<<nwarp1, 256>>>(b1, N);

    // Layer 2
    node2_kernel<<<nblkN, 256>>>(W2, as2, ad2, N);
    agg2_kernel <<<nwarp2, 256>>>(b2, (float*)d_out, N);
}

// round 4
// speedup vs baseline: 1.2715x; 1.1194x over previous
#include <cuda_runtime.h>
#include <cuda_fp16.h>

// Problem constants: N=100000, E=3200000, FEAT=128, HID=32, EMB=16
#define NMAX 100000
#define EMAX 3200000
#define SCAN_B 1024
#define NBLK ((NMAX + SCAN_B - 1) / SCAN_B)   // 98

// ---- scratch (device globals) ----
__device__ __half g_h1h[NMAX * 32];   // layer-1 features, fp16
__device__ float  g_hp1[NMAX * 32];   // layer-1 aggregated output (fp32)
__device__ float  g_als1[NMAX], g_ald1[NMAX];
__device__ __half g_h2h[NMAX * 16];   // layer-2 features, fp16
__device__ float  g_als2[NMAX], g_ald2[NMAX];

__device__ int g_deg [NMAX];
__device__ int g_scan[NMAX];
__device__ int g_off [NMAX];
__device__ int g_pos [NMAX];
__device__ int g_bsum [NBLK];
__device__ int g_bsumx[NBLK];
__device__ int g_esrc[EMAX];

__device__ __forceinline__ float leaky(float a) { return a > 0.0f ? a : 0.2f * a; }

// ===========================================================================
// CSR build
// ===========================================================================
__global__ __launch_bounds__(256) void hist_zero(int N) {
    int i = blockIdx.x * 256 + threadIdx.x;
    if (i < N) g_deg[i] = 0;
}

__global__ __launch_bounds__(256) void hist_kernel(const int* __restrict__ dst, int E) {
    int e = blockIdx.x * 256 + threadIdx.x;
    if (e < E) atomicAdd(&g_deg[__ldg(dst + e)], 1);
}

__global__ __launch_bounds__(SCAN_B) void scan1_kernel(int N) {
    __shared__ int sh[SCAN_B];
    int gid = blockIdx.x * SCAN_B + threadIdx.x;
    int v = (gid < N) ? g_deg[gid] : 0;
    sh[threadIdx.x] = v;
    __syncthreads();
#pragma unroll
    for (int o = 1; o < SCAN_B; o <<= 1) {
        int t = (threadIdx.x >= o) ? sh[threadIdx.x - o] : 0;
        __syncthreads();
        sh[threadIdx.x] += t;
        __syncthreads();
    }
    if (gid < N) g_scan[gid] = sh[threadIdx.x];
    if (threadIdx.x == SCAN_B - 1) g_bsum[blockIdx.x] = sh[SCAN_B - 1];
}

__global__ __launch_bounds__(128) void scan2_kernel(int nb) {
    __shared__ int sh[128];
    int t = threadIdx.x;
    int v = (t < nb) ? g_bsum[t] : 0;
    sh[t] = v;
    __syncthreads();
#pragma unroll
    for (int o = 1; o < 128; o <<= 1) {
        int u = (t >= o) ? sh[t - o] : 0;
        __syncthreads();
        sh[t] += u;
        __syncthreads();
    }
    if (t < nb) g_bsumx[t] = sh[t] - v;
}

__global__ __launch_bounds__(256) void scan3_kernel(int N) {
    int gid = blockIdx.x * 256 + threadIdx.x;
    if (gid < N) {
        int off = g_scan[gid] - g_deg[gid] + g_bsumx[gid / SCAN_B];
        g_off[gid] = off;
        g_pos[gid] = off;
    }
}

__global__ __launch_bounds__(256) void permute_kernel(
    const int* __restrict__ src, const int* __restrict__ dst, int E)
{
    int e = blockIdx.x * 256 + threadIdx.x;
    if (e >= E) return;
    int d = __ldg(dst + e);
    int p = atomicAdd(&g_pos[d], 1);
    g_esrc[p] = __ldg(src + e);
}

// ===========================================================================
// K1: h1 = x @ W1 (-> fp16); al_s1/al_d1. Two nodes per thread.
// ===========================================================================
__global__ __launch_bounds__(256) void node1_kernel(
    const float* __restrict__ x, const float* __restrict__ W1,
    const float* __restrict__ asrc, const float* __restrict__ adst, int N)
{
    __shared__ float Ws[128 * 32];
    __shared__ float s_as[32], s_ad[32];
    for (int i = threadIdx.x; i < 128 * 32; i += 256) Ws[i] = W1[i];
    if (threadIdx.x < 32) { s_as[threadIdx.x] = asrc[threadIdx.x]; s_ad[threadIdx.x] = adst[threadIdx.x]; }
    __syncthreads();

    int n0 = blockIdx.x * 512 + threadIdx.x;
    int n1 = n0 + 256;
    if (n0 >= N) return;
    bool v1 = (n1 < N);
    int n1c = v1 ? n1 : n0;

    float4 acc0[8], acc1[8];
#pragma unroll
    for (int i = 0; i < 8; i++) { acc0[i] = make_float4(0.f,0.f,0.f,0.f); acc1[i] = make_float4(0.f,0.f,0.f,0.f); }

    const float4* xr0 = reinterpret_cast<const float4*>(x + (size_t)n0  * 128);
    const float4* xr1 = reinterpret_cast<const float4*>(x + (size_t)n1c * 128);
#pragma unroll 2
    for (int k4 = 0; k4 < 32; k4++) {
        float4 xv0 = __ldg(&xr0[k4]);
        float4 xv1 = __ldg(&xr1[k4]);
        float xk0[4] = {xv0.x, xv0.y, xv0.z, xv0.w};
        float xk1[4] = {xv1.x, xv1.y, xv1.z, xv1.w};
#pragma unroll
        for (int kk = 0; kk < 4; kk++) {
            const float4* wr = reinterpret_cast<const float4*>(&Ws[(k4 * 4 + kk) * 32]);
            float xs0 = xk0[kk], xs1 = xk1[kk];
#pragma unroll
            for (int c4 = 0; c4 < 8; c4++) {
                float4 w = wr[c4];
                acc0[c4].x = fmaf(xs0, w.x, acc0[c4].x); acc0[c4].y = fmaf(xs0, w.y, acc0[c4].y);
                acc0[c4].z = fmaf(xs0, w.z, acc0[c4].z); acc0[c4].w = fmaf(xs0, w.w, acc0[c4].w);
                acc1[c4].x = fmaf(xs1, w.x, acc1[c4].x); acc1[c4].y = fmaf(xs1, w.y, acc1[c4].y);
                acc1[c4].z = fmaf(xs1, w.z, acc1[c4].z); acc1[c4].w = fmaf(xs1, w.w, acc1[c4].w);
            }
        }
    }

    float als0 = 0.f, ald0 = 0.f, als1v = 0.f, ald1v = 0.f;
#pragma unroll
    for (int c4 = 0; c4 < 8; c4++) {
        float4 s4 = reinterpret_cast<const float4*>(s_as)[c4];
        float4 d4 = reinterpret_cast<const float4*>(s_ad)[c4];
        float4 a = acc0[c4];
        als0 += a.x*s4.x + a.y*s4.y + a.z*s4.z + a.w*s4.w;
        ald0 += a.x*d4.x + a.y*d4.y + a.z*d4.z + a.w*d4.w;
        float4 b = acc1[c4];
        als1v += b.x*s4.x + b.y*s4.y + b.z*s4.z + b.w*s4.w;
        ald1v += b.x*d4.x + b.y*d4.y + b.z*d4.z + b.w*d4.w;
    }
    g_als1[n0] = als0; g_ald1[n0] = ald0;

    __half2* hp0 = reinterpret_cast<__half2*>(&g_h1h[n0 * 32]);
#pragma unroll
    for (int c4 = 0; c4 < 8; c4++) {
        hp0[c4 * 2]     = __floats2half2_rn(acc0[c4].x, acc0[c4].y);
        hp0[c4 * 2 + 1] = __floats2half2_rn(acc0[c4].z, acc0[c4].w);
    }
    if (v1) {
        g_als1[n1] = als1v; g_ald1[n1] = ald1v;
        __half2* hp1 = reinterpret_cast<__half2*>(&g_h1h[n1 * 32]);
#pragma unroll
        for (int c4 = 0; c4 < 8; c4++) {
            hp1[c4 * 2]     = __floats2half2_rn(acc1[c4].x, acc1[c4].y);
            hp1[c4 * 2 + 1] = __floats2half2_rn(acc1[c4].z, acc1[c4].w);
        }
    }
}

// ===========================================================================
// K2: layer-1 aggregate. TWO nodes per warp, 16 lanes each, lane = 2 channels.
// ===========================================================================
__global__ __launch_bounds__(256) void agg1_kernel(const float* __restrict__ b1, int N)
{
    int wid = (blockIdx.x * 256 + threadIdx.x) >> 5;
    int lane = threadIdx.x & 31;
    int half = lane >> 4;       // which node in this warp
    int l16 = lane & 15;        // lane within node group (channel pair index)
    int n = wid * 2 + half;
    if (wid * 2 >= N) return;
    bool nvalid = (n < N);
    int nn = nvalid ? n : (N - 1);

    float ald = __ldg(&g_ald1[nn]);
    int start = g_off[nn];
    int deg = g_deg[nn];
    int end = start + deg;

    int nb = (deg + 15) >> 4;
    { int t = __shfl_xor_sync(0xffffffffu, nb, 16); nb = nb > t ? nb : t; }

    float2 a0 = make_float2(0.f, 0.f), a1 = make_float2(0.f, 0.f);
    float den = 0.f;
    const __half2* h1p = reinterpret_cast<const __half2*>(g_h1h);
    for (int b = 0; b < nb; b++) {
        int idx = start + b * 16 + l16;
        int s = 0; float w = 0.f;
        if (nvalid && idx < end) {
            s = __ldg(&g_esrc[idx]);
            w = __expf(leaky(__ldg(&g_als1[s]) + ald));
        }
        den += w;
#pragma unroll
        for (int j = 0; j < 16; j += 2) {
            int   s0 = __shfl_sync(0xffffffffu, s, j, 16);
            int   s1 = __shfl_sync(0xffffffffu, s, j + 1, 16);
            float w0 = __shfl_sync(0xffffffffu, w, j, 16);
            float w1 = __shfl_sync(0xffffffffu, w, j + 1, 16);
            float2 f0 = (w0 != 0.f) ? __half22float2(__ldg(&h1p[s0 * 16 + l16]))
                                    : make_float2(0.f, 0.f);
            float2 f1 = (w1 != 0.f) ? __half22float2(__ldg(&h1p[s1 * 16 + l16]))
                                    : make_float2(0.f, 0.f);
            a0.x = fmaf(w0, f0.x, a0.x); a0.y = fmaf(w0, f0.y, a0.y);
            a1.x = fmaf(w1, f1.x, a1.x); a1.y = fmaf(w1, f1.y, a1.y);
        }
    }
    float2 acc = make_float2(a0.x + a1.x, a0.y + a1.y);
#pragma unroll
    for (int o = 8; o; o >>= 1) den += __shfl_xor_sync(0xffffffffu, den, o, 16);

    float wself = __expf(leaky(__ldg(&g_als1[nn]) + ald));
    den += wself;
    float2 hs = __half22float2(__ldg(&h1p[nn * 16 + l16]));
    acc.x = fmaf(wself, hs.x, acc.x);
    acc.y = fmaf(wself, hs.y, acc.y);

    float inv = 1.0f / (den + 1e-16f);
    if (nvalid) {
        float2 bv = __ldg(&reinterpret_cast<const float2*>(b1)[l16]);
        float2 r;
        r.x = fmaxf(fmaf(acc.x, inv, bv.x), 0.f);
        r.y = fmaxf(fmaf(acc.y, inv, bv.y), 0.f);
        reinterpret_cast<float2*>(&g_hp1[n * 32])[l16] = r;
    }
}

// ===========================================================================
// K3: h2 = h' @ W2 (-> fp16); al_s2/al_d2
// ===========================================================================
__global__ __launch_bounds__(256) void node2_kernel(
    const float* __restrict__ W2,
    const float* __restrict__ asrc, const float* __restrict__ adst, int N)
{
    __shared__ float Ws[32 * 16];
    __shared__ float s_as[16], s_ad[16];
    for (int i = threadIdx.x; i < 32 * 16; i += 256) Ws[i] = W2[i];
    if (threadIdx.x < 16) { s_as[threadIdx.x] = asrc[threadIdx.x]; s_ad[threadIdx.x] = adst[threadIdx.x]; }
    __syncthreads();

    int n = blockIdx.x * 256 + threadIdx.x;
    if (n >= N) return;

    float4 h2[4];
#pragma unroll
    for (int i = 0; i < 4; i++) h2[i] = make_float4(0.f, 0.f, 0.f, 0.f);

    const float4* hp = reinterpret_cast<const float4*>(&g_hp1[n * 32]);
#pragma unroll
    for (int c4 = 0; c4 < 8; c4++) {
        float4 xv = hp[c4];
        float xk[4] = {xv.x, xv.y, xv.z, xv.w};
#pragma unroll
        for (int kk = 0; kk < 4; kk++) {
            const float4* wr = reinterpret_cast<const float4*>(&Ws[(c4 * 4 + kk) * 16]);
            float xs = xk[kk];
#pragma unroll
            for (int o4 = 0; o4 < 4; o4++) {
                float4 w = wr[o4];
                h2[o4].x = fmaf(xs, w.x, h2[o4].x); h2[o4].y = fmaf(xs, w.y, h2[o4].y);
                h2[o4].z = fmaf(xs, w.z, h2[o4].z); h2[o4].w = fmaf(xs, w.w, h2[o4].w);
            }
        }
    }

    float als = 0.f, ald = 0.f;
#pragma unroll
    for (int o4 = 0; o4 < 4; o4++) {
        float4 a  = h2[o4];
        float4 s4 = reinterpret_cast<const float4*>(s_as)[o4];
        float4 d4 = reinterpret_cast<const float4*>(s_ad)[o4];
        als += a.x*s4.x + a.y*s4.y + a.z*s4.z + a.w*s4.w;
        ald += a.x*d4.x + a.y*d4.y + a.z*d4.z + a.w*d4.w;
    }
    g_als2[n] = als; g_ald2[n] = ald;

    __half2* out = reinterpret_cast<__half2*>(&g_h2h[n * 16]);
#pragma unroll
    for (int o4 = 0; o4 < 4; o4++) {
        out[o4 * 2]     = __floats2half2_rn(h2[o4].x, h2[o4].y);
        out[o4 * 2 + 1] = __floats2half2_rn(h2[o4].z, h2[o4].w);
    }
}

// ===========================================================================
// K4: layer-2 aggregate + output. FOUR nodes per warp, 8 lanes each.
// ===========================================================================
__global__ __launch_bounds__(256) void agg2_kernel(
    const float* __restrict__ b2, float* __restrict__ out, int N)
{
    int wid = (blockIdx.x * 256 + threadIdx.x) >> 5;
    int lane = threadIdx.x & 31;
    int quad = lane >> 3;       // which node in this warp (0..3)
    int l8 = lane & 7;          // channel pair index (0..7)
    int n = wid * 4 + quad;
    if (wid * 4 >= N) return;
    bool nvalid = (n < N);
    int nn = nvalid ? n : (N - 1);

    float ald = __ldg(&g_ald2[nn]);
    int start = g_off[nn];
    int deg = g_deg[nn];
    int end = start + deg;

    int nb = (deg + 7) >> 3;
    { int t = __shfl_xor_sync(0xffffffffu, nb, 8);  nb = nb > t ? nb : t; }
    { int t = __shfl_xor_sync(0xffffffffu, nb, 16); nb = nb > t ? nb : t; }

    float2 a0 = make_float2(0.f, 0.f), a1 = make_float2(0.f, 0.f);
    float den = 0.f;
    const __half2* h2p = reinterpret_cast<const __half2*>(g_h2h);
    for (int b = 0; b < nb; b++) {
        int idx = start + b * 8 + l8;
        int s = 0; float w = 0.f;
        if (nvalid && idx < end) {
            s = __ldg(&g_esrc[idx]);
            w = __expf(leaky(__ldg(&g_als2[s]) + ald));
        }
        den += w;
#pragma unroll
        for (int j = 0; j < 8; j += 2) {
            int   s0 = __shfl_sync(0xffffffffu, s, j, 8);
            int   s1 = __shfl_sync(0xffffffffu, s, j + 1, 8);
            float w0 = __shfl_sync(0xffffffffu, w, j, 8);
            float w1 = __shfl_sync(0xffffffffu, w, j + 1, 8);
            float2 f0 = (w0 != 0.f) ? __half22float2(__ldg(&h2p[s0 * 8 + l8]))
                                    : make_float2(0.f, 0.f);
            float2 f1 = (w1 != 0.f) ? __half22float2(__ldg(&h2p[s1 * 8 + l8]))
                                    : make_float2(0.f, 0.f);
            a0.x = fmaf(w0, f0.x, a0.x); a0.y = fmaf(w0, f0.y, a0.y);
            a1.x = fmaf(w1, f1.x, a1.x); a1.y = fmaf(w1, f1.y, a1.y);
        }
    }
    float2 acc = make_float2(a0.x + a1.x, a0.y + a1.y);
#pragma unroll
    for (int o = 4; o; o >>= 1) den += __shfl_xor_sync(0xffffffffu, den, o, 8);

    float wself = __expf(leaky(__ldg(&g_als2[nn]) + ald));
    den += wself;
    float2 hs = __half22float2(__ldg(&h2p[nn * 8 + l8]));
    acc.x = fmaf(wself, hs.x, acc.x);
    acc.y = fmaf(wself, hs.y, acc.y);

    float inv = 1.0f / (den + 1e-16f);
    if (nvalid) {
        float2 bv = __ldg(&reinterpret_cast<const float2*>(b2)[l8]);
        float2 r;
        r.x = fmaf(acc.x, inv, bv.x);
        r.y = fmaf(acc.y, inv, bv.y);
        reinterpret_cast<float2*>(&out[n * 16])[l8] = r;
    }
}

// ===========================================================================
extern "C" void kernel_launch(void* const* d_in, const int* in_sizes, int n_in,
                              void* d_out, int out_size)
{
    const float* x   = (const float*)d_in[0];
    const int*   ei  = (const int*)  d_in[1];
    const float* W1  = (const float*)d_in[3];
    const float* as1 = (const float*)d_in[4];
    const float* ad1 = (const float*)d_in[5];
    const float* b1  = (const float*)d_in[6];
    const float* W2  = (const float*)d_in[7];
    const float* as2 = (const float*)d_in[8];
    const float* ad2 = (const float*)d_in[9];
    const float* b2  = (const float*)d_in[10];

    int N = in_sizes[0] / 128;
    int E = in_sizes[1] / 2;
    const int* src = ei;
    const int* dst = ei + E;

    int nblkN  = (N + 255) / 256;
    int nblkE  = (E + 255) / 256;
    int nscan  = (N + SCAN_B - 1) / SCAN_B;
    int nwarp1 = (((N + 1) / 2) * 32 + 255) / 256;
    int nwarp2 = (((N + 3) / 4) * 32 + 255) / 256;

    // CSR build (shared by both layers)
    hist_zero   <<<nblkN, 256>>>(N);
    hist_kernel <<<nblkE, 256>>>(dst, E);
    scan1_kernel<<<nscan, SCAN_B>>>(N);
    scan2_kernel<<<1, 128>>>(nscan);
    scan3_kernel<<<nblkN, 256>>>(N);
    permute_kernel<<<nblkE, 256>>>(src, dst, E);

    // Layer 1
    node1_kernel<<<(N + 511) / 512, 256>>>(x, W1, as1, ad1, N);
    agg1_kernel <<<nwarp1, 256>>>(b1, N);

    // Layer 2
    node2_kernel<<<nblkN, 256>>>(W2, as2, ad2, N);
    agg2_kernel <<<nwarp2, 256>>>(b2, (float*)d_out, N);
}